// round 5
// baseline (speedup 1.0000x reference)
#include <cuda_runtime.h>

#define BD 4
#define CD 256
#define HD 56
#define WD 56
#define GD 16
#define GCD 16
#define KD 3
#define NSD 2
#define POSN (BD*HD*WD)   // 12544
#define IN1 2112
#define OUT1 96
#define OWD 112

// Scratch (device globals: no cudaMalloc allowed)
__device__ float g_desc[(size_t)IN1 * POSN];   // [feature][pos]  ~106 MB
__device__ float g_r[(size_t)POSN * OUT1];     // [pos][96]       ~4.8 MB

// ---------------------------------------------------------------------------
// Scrambled-unfold tap semantics (matches the ACTUAL reference code):
//   for output pos (h2, w2), tap (kh, kw):
//     m = kw*56 + h2;  h = m/3;  j = m%3
//     T[gc][kh][kw] = x[b, c, h + kh - 1, w2 + j - 1]   (0 outside)
// We stage xs[gc][kw][kh][wp] = x[b, c, h(kw)+kh-1, wp-1]; tap = xs[gc][kw][kh][w2 + j(kw)]
// ---------------------------------------------------------------------------

__device__ __forceinline__ void load_taps(const float* __restrict__ x,
                                          int b, int g, int h2,
                                          float (*xs)[3][3][58], int tid) {
    for (int idx = tid; idx < GCD * 9 * 58; idx += 128) {
        int wp = idx % 58;
        int t  = idx / 58;          // [0,144)
        int kh = t % 3;
        int kw = (t / 3) % 3;
        int gc = t / 9;
        int m  = kw * 56 + h2;
        int hh = m / 3 + kh - 1;
        int ww = wp - 1;
        float v = 0.f;
        if (hh >= 0 && hh < HD && ww >= 0 && ww < WD)
            v = x[(((size_t)b*CD + g*GCD + gc)*HD + hh)*WD + ww];
        xs[gc][kw][kh][wp] = v;
    }
}

// ---------------------------------------------------------------------------
// K1: build descriptor  desc[feature][pos]
//   x1 (g*36 + jc*9 + kh*3 + kw): max over channels {jc, jc+4, jc+8, jc+12}
//   x2 (576  + g*48 + gc*3 + kw): max over kh
//   x3 (1344 + g*48 + gc*3 + kh): max over kw
// ---------------------------------------------------------------------------
__global__ __launch_bounds__(128) void desc_kernel(const float* __restrict__ x) {
    const int g = blockIdx.x, h2 = blockIdx.y, b = blockIdx.z;
    __shared__ float xs[GCD][3][3][58];   // 33408 B

    const int tid = threadIdx.x;
    load_taps(x, b, g, h2, xs, tid);
    __syncthreads();

    const int jv0 = h2 % 3, jv1 = (56 + h2) % 3, jv2 = (112 + h2) % 3;
    const int posBase = (b*HD + h2)*WD;

    // x2 / x3: items = (gc, w)
    for (int it = tid; it < GCD * WD; it += 128) {
        int w  = it % WD;
        int gc = it / WD;
        float T[3][3];
        #pragma unroll
        for (int kh = 0; kh < 3; kh++) {
            T[kh][0] = xs[gc][0][kh][w + jv0];
            T[kh][1] = xs[gc][1][kh][w + jv1];
            T[kh][2] = xs[gc][2][kh][w + jv2];
        }
        #pragma unroll
        for (int kw = 0; kw < 3; kw++) {
            float m = fmaxf(T[0][kw], fmaxf(T[1][kw], T[2][kw]));   // max over kh
            g_desc[(size_t)(576 + g*48 + gc*3 + kw)*POSN + posBase + w] = m;
        }
        #pragma unroll
        for (int kh = 0; kh < 3; kh++) {
            float m = fmaxf(T[kh][0], fmaxf(T[kh][1], T[kh][2]));   // max over kw
            g_desc[(size_t)(1344 + g*48 + gc*3 + kh)*POSN + posBase + w] = m;
        }
    }

    // x1: items = (jc, w), strided max over channels {jc, jc+4, jc+8, jc+12}
    for (int it = tid; it < 4 * WD; it += 128) {
        int w  = it % WD;
        int jc = it / WD;
        const int jvv[3] = {jv0, jv1, jv2};
        #pragma unroll
        for (int kh = 0; kh < 3; kh++) {
            #pragma unroll
            for (int kw = 0; kw < 3; kw++) {
                int wp = w + jvv[kw];
                float m = xs[jc][kw][kh][wp];
                m = fmaxf(m, xs[jc + 4 ][kw][kh][wp]);
                m = fmaxf(m, xs[jc + 8 ][kw][kh][wp]);
                m = fmaxf(m, xs[jc + 12][kw][kh][wp]);
                g_desc[(size_t)(g*36 + jc*9 + kh*3 + kw)*POSN + posBase + w] = m;
            }
        }
    }
}

// ---------------------------------------------------------------------------
// K2: r[pos][96] = relu( (desc^T @ w1^T) * scale + bias )
// Tile: BM=64, BN=96(all), BK=32, 256 threads, 4x6 per-thread tile
// ---------------------------------------------------------------------------
#define BM 64
#define BK 32

__global__ __launch_bounds__(256) void gemm_kernel(
    const float* __restrict__ w1,
    const float* __restrict__ gamma, const float* __restrict__ beta,
    const float* __restrict__ mean,  const float* __restrict__ var)
{
    __shared__ __align__(16) float As[BK][BM];      // [k][m]
    __shared__ float Bs[BK][97];                    // [k][n], padded

    const int tid = threadIdx.x;
    const int tx = tid % 16;           // -> cols tx + 16*j
    const int ty = tid / 16;           // -> rows ty + 16*i
    const int row0 = blockIdx.x * BM;

    float acc[4][6];
    #pragma unroll
    for (int i = 0; i < 4; i++)
        #pragma unroll
        for (int j = 0; j < 6; j++) acc[i][j] = 0.f;

    for (int k0 = 0; k0 < IN1; k0 += BK) {
        #pragma unroll
        for (int i = 0; i < 2; i++) {
            int idx4 = tid + i * 256;
            int mq = idx4 % 16, k = idx4 / 16;
            float4 v = *reinterpret_cast<const float4*>(
                &g_desc[(size_t)(k0 + k)*POSN + row0 + mq*4]);
            *reinterpret_cast<float4*>(&As[k][mq*4]) = v;
        }
        #pragma unroll
        for (int i = 0; i < 3; i++) {
            int idx4 = tid + i * 256;
            int kq = idx4 % 8, n = idx4 / 8;
            float4 v = *reinterpret_cast<const float4*>(&w1[n*IN1 + k0 + kq*4]);
            Bs[kq*4 + 0][n] = v.x;
            Bs[kq*4 + 1][n] = v.y;
            Bs[kq*4 + 2][n] = v.z;
            Bs[kq*4 + 3][n] = v.w;
        }
        __syncthreads();

        #pragma unroll
        for (int kk = 0; kk < BK; kk++) {
            float a[4], bb[6];
            #pragma unroll
            for (int i = 0; i < 4; i++) a[i] = As[kk][ty + 16*i];
            #pragma unroll
            for (int j = 0; j < 6; j++) bb[j] = Bs[kk][tx + 16*j];
            #pragma unroll
            for (int i = 0; i < 4; i++)
                #pragma unroll
                for (int j = 0; j < 6; j++)
                    acc[i][j] = fmaf(a[i], bb[j], acc[i][j]);
        }
        __syncthreads();
    }

    // Fused BN + ReLU epilogue
    #pragma unroll
    for (int j = 0; j < 6; j++) {
        int n = tx + 16*j;
        float s  = gamma[n] * rsqrtf(var[n] + 1e-5f);
        float bi = beta[n] - mean[n] * s;
        #pragma unroll
        for (int i = 0; i < 4; i++) {
            int m = row0 + ty + 16*i;
            float v = fmaf(acc[i][j], s, bi);
            g_r[(size_t)m*OUT1 + n] = v > 0.f ? v : 0.f;
        }
    }
}

// ---------------------------------------------------------------------------
// K3: per (g, h2, b): wa = w2_g @ r + b2, wb = w3_g @ r + b3,
//     wt[kk][nh][nw] = wa[kh*2+nh]*wb[kw*2+nw], softmax over kk,
//     out = mean over kk of tap * wt, interleaved write [B,C,2H,2W]
// bufA is a union: rs (stage 1 only) then xs (stage 3 only).
// ---------------------------------------------------------------------------
__global__ __launch_bounds__(128) void apply_kernel(
    const float* __restrict__ x,
    const float* __restrict__ w2, const float* __restrict__ b2,
    const float* __restrict__ w3, const float* __restrict__ b3,
    float* __restrict__ out)
{
    const int g = blockIdx.x, h2 = blockIdx.y, b = blockIdx.z;
    __shared__ float bufA[GCD*3*3*58];      // 33408 B: rs (5432 fl) then xs (8352 fl)
    __shared__ float w2s[6][96];            // 2304 B
    __shared__ float w3s[6][96];            // 2304 B
    __shared__ float b2s[6], b3s[6];
    __shared__ float wab[WD][12];           // wa[0..5], wb[6..11]; 2688 B
    __shared__ float sms[WD][4][9];         // softmax probs / 9;    8064 B

    float* rs = bufA;                                            // [WD][97]
    float (*xs)[3][3][58] = reinterpret_cast<float(*)[3][3][58]>(bufA);

    const int tid = threadIdx.x;
    const int posBase = (b*HD + h2)*WD;

    // Phase 0: load r row (coalesced) + weights
    for (int idx = tid; idx < WD * OUT1; idx += 128) {
        int w = idx / OUT1, j = idx % OUT1;
        rs[w*97 + j] = g_r[(size_t)posBase*OUT1 + idx];
    }
    for (int idx = tid; idx < 6 * 96; idx += 128) {
        int q = idx / 96, j = idx % 96;
        w2s[q][j] = w2[(g*6 + q)*OUT1 + j];
        w3s[q][j] = w3[(g*6 + q)*OUT1 + j];
    }
    if (tid < 6) {
        b2s[tid] = b2[g*6 + tid];
        b3s[tid] = b3[g*6 + tid];
    }
    __syncthreads();

    // Phase 1: wa/wb matvecs. items = (w, q) with q in [0,12)
    for (int it = tid; it < WD * 12; it += 128) {
        int q = it % 12;
        int w = it / 12;
        float acc = 0.f;
        if (q < 6) {
            #pragma unroll 8
            for (int j = 0; j < 96; j++) acc = fmaf(w2s[q][j], rs[w*97 + j], acc);
            acc += b2s[q];
        } else {
            int qq = q - 6;
            #pragma unroll 8
            for (int j = 0; j < 96; j++) acc = fmaf(w3s[qq][j], rs[w*97 + j], acc);
            acc += b3s[qq];
        }
        wab[w][q] = acc;
    }
    __syncthreads();   // rs dead from here; bufA reused as xs

    // Phase 2a: softmax over kk=9 per (w, nh, nw); pre-divide by 9 (mean)
    for (int it = tid; it < WD * 4; it += 128) {
        int t = it % 4;          // t = nh*2 + nw
        int w = it / 4;
        int nh = t >> 1, nw = t & 1;
        float e[9], m = -1e30f;
        #pragma unroll
        for (int kk = 0; kk < 9; kk++) {
            int kh = kk / 3, kw = kk % 3;
            e[kk] = wab[w][kh*2 + nh] * wab[w][6 + kw*2 + nw];
            m = fmaxf(m, e[kk]);
        }
        float s = 0.f;
        #pragma unroll
        for (int kk = 0; kk < 9; kk++) { e[kk] = expf(e[kk] - m); s += e[kk]; }
        float inv = 1.f / (s * 9.f);
        #pragma unroll
        for (int kk = 0; kk < 9; kk++) sms[w][t][kk] = e[kk] * inv;
    }
    // Phase 2b (same phase): load scrambled taps into xs (overwrites rs)
    load_taps(x, b, g, h2, xs, tid);
    __syncthreads();

    const int jv0 = h2 % 3, jv1 = (56 + h2) % 3, jv2 = (112 + h2) % 3;
    const int jvv[3] = {jv0, jv1, jv2};

    // Phase 3: apply dynamic kernel. items = (gc, w)
    for (int it = tid; it < GCD * WD; it += 128) {
        int w  = it % WD;
        int gc = it / WD;
        float o[4] = {0.f, 0.f, 0.f, 0.f};
        #pragma unroll
        for (int kk = 0; kk < 9; kk++) {
            int kh = kk / 3, kw = kk % 3;
            float u = xs[gc][kw][kh][w + jvv[kw]];
            #pragma unroll
            for (int t = 0; t < 4; t++)
                o[t] = fmaf(u, sms[w][t][kk], o[t]);
        }
        int c = g*GCD + gc;
        #pragma unroll
        for (int t = 0; t < 4; t++) {
            int nh = t >> 1, nw = t & 1;
            out[(((size_t)b*CD + c)*OWD + 2*h2 + nh)*OWD + 2*w + nw] = o[t];
        }
    }
}

// ---------------------------------------------------------------------------
extern "C" void kernel_launch(void* const* d_in, const int* in_sizes, int n_in,
                              void* d_out, int out_size) {
    const float* x     = (const float*)d_in[0];
    const float* w1    = (const float*)d_in[1];
    const float* gamma = (const float*)d_in[2];
    const float* beta  = (const float*)d_in[3];
    const float* mean  = (const float*)d_in[4];
    const float* var   = (const float*)d_in[5];
    const float* w2    = (const float*)d_in[6];
    const float* b2    = (const float*)d_in[7];
    const float* w3    = (const float*)d_in[8];
    const float* b3    = (const float*)d_in[9];
    float* out = (float*)d_out;

    dim3 gridA(GD, HD, BD);   // (16, 56, 4)
    desc_kernel<<<gridA, 128>>>(x);
    gemm_kernel<<<POSN / BM, 256>>>(w1, gamma, beta, mean, var);
    apply_kernel<<<gridA, 128>>>(x, w2, b2, w3, b3, out);
}

// round 6
// speedup vs baseline: 1.0281x; 1.0281x over previous
#include <cuda_runtime.h>
#include <cstdint>

#define BD 4
#define CD 256
#define HD 56
#define WD 56
#define GD 16
#define GCD 16
#define POSN (BD*HD*WD)   // 12544
#define IN1 2112
#define OUT1 96
#define OWD 112

// Scratch (device globals: no cudaMalloc allowed)
__device__ float g_desc[(size_t)IN1 * POSN];   // [feature][pos]  ~106 MB
__device__ float g_r[(size_t)POSN * OUT1];     // [pos][96]       ~4.8 MB

// ---------------------------------------------------------------------------
// Scrambled-unfold tap semantics (matches the ACTUAL reference code):
//   for output pos (h2, w2), tap (kh, kw):
//     m = kw*56 + h2;  h = m/3;  j = m%3
//     T[gc][kh][kw] = x[b, c, h + kh - 1, w2 + j - 1]   (0 outside)
// ---------------------------------------------------------------------------
__device__ __forceinline__ void load_taps(const float* __restrict__ x,
                                          int b, int g, int h2,
                                          float (*xs)[3][3][58], int tid) {
    const unsigned cbase = (unsigned)(b*CD + g*GCD);
    for (int idx = tid; idx < GCD * 9 * 58; idx += 128) {
        int wp = idx % 58;
        int t  = idx / 58;          // [0,144)
        int kh = t % 3;
        int kw = (t / 3) % 3;
        int gc = t / 9;
        int m  = kw * 56 + h2;
        int hh = m / 3 + kh - 1;
        int ww = wp - 1;
        float v = 0.f;
        if (hh >= 0 && hh < HD && ww >= 0 && ww < WD)
            v = x[((cbase + gc)*HD + hh)*WD + ww];
        xs[gc][kw][kh][wp] = v;
    }
}

// ---------------------------------------------------------------------------
// K1: build descriptor  desc[feature][pos]
// ---------------------------------------------------------------------------
__global__ __launch_bounds__(128) void desc_kernel(const float* __restrict__ x) {
    const int g = blockIdx.x, h2 = blockIdx.y, b = blockIdx.z;
    __shared__ float xs[GCD][3][3][58];   // 33408 B

    const int tid = threadIdx.x;
    load_taps(x, b, g, h2, xs, tid);
    __syncthreads();

    const int jv0 = h2 % 3, jv1 = (56 + h2) % 3, jv2 = (112 + h2) % 3;
    const unsigned posBase = (unsigned)(b*HD + h2)*WD;

    // x2 / x3: items = (gc, w)
    for (int it = tid; it < GCD * WD; it += 128) {
        int w  = it % WD;
        int gc = it / WD;
        float T[3][3];
        #pragma unroll
        for (int kh = 0; kh < 3; kh++) {
            T[kh][0] = xs[gc][0][kh][w + jv0];
            T[kh][1] = xs[gc][1][kh][w + jv1];
            T[kh][2] = xs[gc][2][kh][w + jv2];
        }
        unsigned f2 = (unsigned)(576 + g*48 + gc*3);
        unsigned f3 = (unsigned)(1344 + g*48 + gc*3);
        #pragma unroll
        for (int kw = 0; kw < 3; kw++) {
            float m = fmaxf(T[0][kw], fmaxf(T[1][kw], T[2][kw]));   // max over kh
            g_desc[(f2 + kw)*POSN + posBase + w] = m;
        }
        #pragma unroll
        for (int kh = 0; kh < 3; kh++) {
            float m = fmaxf(T[kh][0], fmaxf(T[kh][1], T[kh][2]));   // max over kw
            g_desc[(f3 + kh)*POSN + posBase + w] = m;
        }
    }

    // x1: items = (jc, w), strided max over channels {jc, jc+4, jc+8, jc+12}
    const int jvv[3] = {jv0, jv1, jv2};
    for (int it = tid; it < 4 * WD; it += 128) {
        int w  = it % WD;
        int jc = it / WD;
        unsigned f1 = (unsigned)(g*36 + jc*9);
        #pragma unroll
        for (int kh = 0; kh < 3; kh++) {
            #pragma unroll
            for (int kw = 0; kw < 3; kw++) {
                int wp = w + jvv[kw];
                float m = xs[jc][kw][kh][wp];
                m = fmaxf(m, xs[jc + 4 ][kw][kh][wp]);
                m = fmaxf(m, xs[jc + 8 ][kw][kh][wp]);
                m = fmaxf(m, xs[jc + 12][kw][kh][wp]);
                g_desc[(f1 + kh*3 + kw)*POSN + posBase + w] = m;
            }
        }
    }
}

// ---------------------------------------------------------------------------
// K2: tensor-core TF32 GEMM (3xTF32 split for fp32-grade accuracy)
// r[m][96] = relu(BN( desc^T[m][k] @ w1^T[k][n] ))
// Block: BM=128, BN=96 (all), BK=16. 256 threads = 8 warps as 4(m) x 2(n).
// Warp tile: 2 mtiles(16) x 6 ntiles(8) of mma.m16n8k8.
// ---------------------------------------------------------------------------
#define GBM 128
#define GBK 16
#define APAD 136
#define BPAD 104

__device__ __forceinline__ uint32_t f2tf32(float f) {
    uint32_t r;
    asm("cvt.rna.tf32.f32 %0, %1;" : "=r"(r) : "f"(f));
    return r;
}

__device__ __forceinline__ void mma_tf32(float* c, const uint32_t* a, const uint32_t* b) {
    asm volatile(
        "mma.sync.aligned.m16n8k8.row.col.f32.tf32.tf32.f32 "
        "{%0,%1,%2,%3}, {%4,%5,%6,%7}, {%8,%9}, {%0,%1,%2,%3};"
        : "+f"(c[0]), "+f"(c[1]), "+f"(c[2]), "+f"(c[3])
        : "r"(a[0]), "r"(a[1]), "r"(a[2]), "r"(a[3]), "r"(b[0]), "r"(b[1]));
}

__global__ __launch_bounds__(256) void gemm_tc_kernel(
    const float* __restrict__ w1,
    const float* __restrict__ gamma, const float* __restrict__ beta,
    const float* __restrict__ mean,  const float* __restrict__ var)
{
    __shared__ float Ah[GBK][APAD], Al[GBK][APAD];   // 2 * 8704 B
    __shared__ float Bh[GBK][BPAD], Bl[GBK][BPAD];   // 2 * 6656 B

    const int tid  = threadIdx.x;
    const int warp = tid >> 5;
    const int lane = tid & 31;
    const int wm = warp & 3;          // 0..3  (m)
    const int wn = warp >> 2;         // 0..1  (n)
    const int ar = lane >> 2;         // 0..7
    const int ac = lane & 3;          // 0..3
    const unsigned row0 = blockIdx.x * GBM;

    float c[2][6][4];
    #pragma unroll
    for (int mt = 0; mt < 2; mt++)
        #pragma unroll
        for (int nt = 0; nt < 6; nt++)
            #pragma unroll
            for (int q = 0; q < 4; q++) c[mt][nt][q] = 0.f;

    for (int k0 = 0; k0 < IN1; k0 += GBK) {
        // A tile: 16 k-rows x 128 m. 512 float4, 2 per thread, coalesced on m.
        #pragma unroll
        for (int i = 0; i < 2; i++) {
            int idx4 = tid + (i << 8);
            int m4 = idx4 & 31;        // 32 float4 per row
            int k  = idx4 >> 5;
            float4 v = *reinterpret_cast<const float4*>(
                &g_desc[(unsigned)(k0 + k)*POSN + row0 + m4*4]);
            float* dh = &Ah[k][m4*4];
            float* dl = &Al[k][m4*4];
            float h0 = __uint_as_float(f2tf32(v.x)); dh[0]=h0; dl[0]=__uint_as_float(f2tf32(v.x-h0));
            float h1 = __uint_as_float(f2tf32(v.y)); dh[1]=h1; dl[1]=__uint_as_float(f2tf32(v.y-h1));
            float h2 = __uint_as_float(f2tf32(v.z)); dh[2]=h2; dl[2]=__uint_as_float(f2tf32(v.z-h2));
            float h3 = __uint_as_float(f2tf32(v.w)); dh[3]=h3; dl[3]=__uint_as_float(f2tf32(v.w-h3));
        }
        // B tile: 96 n x 16 k. 1536 floats, 6 per thread.
        #pragma unroll
        for (int i = 0; i < 6; i++) {
            int idx = tid + (i << 8);
            int k = idx & 15;
            int n = idx >> 4;
            float v = w1[(unsigned)n*IN1 + k0 + k];
            float h = __uint_as_float(f2tf32(v));
            Bh[k][n] = h;
            Bl[k][n] = __uint_as_float(f2tf32(v - h));
        }
        __syncthreads();

        #pragma unroll
        for (int ks = 0; ks < 2; ks++) {
            const int kb = ks * 8;
            uint32_t ah[2][4], al[2][4];
            #pragma unroll
            for (int mt = 0; mt < 2; mt++) {
                int mrow = wm*32 + mt*16 + ar;
                ah[mt][0] = __float_as_uint(Ah[kb+ac  ][mrow  ]);
                ah[mt][1] = __float_as_uint(Ah[kb+ac  ][mrow+8]);
                ah[mt][2] = __float_as_uint(Ah[kb+ac+4][mrow  ]);
                ah[mt][3] = __float_as_uint(Ah[kb+ac+4][mrow+8]);
                al[mt][0] = __float_as_uint(Al[kb+ac  ][mrow  ]);
                al[mt][1] = __float_as_uint(Al[kb+ac  ][mrow+8]);
                al[mt][2] = __float_as_uint(Al[kb+ac+4][mrow  ]);
                al[mt][3] = __float_as_uint(Al[kb+ac+4][mrow+8]);
            }
            uint32_t bh[6][2], bl[6][2];
            #pragma unroll
            for (int nt = 0; nt < 6; nt++) {
                int n = wn*48 + nt*8 + ar;
                bh[nt][0] = __float_as_uint(Bh[kb+ac  ][n]);
                bh[nt][1] = __float_as_uint(Bh[kb+ac+4][n]);
                bl[nt][0] = __float_as_uint(Bl[kb+ac  ][n]);
                bl[nt][1] = __float_as_uint(Bl[kb+ac+4][n]);
            }
            #pragma unroll
            for (int mt = 0; mt < 2; mt++)
                #pragma unroll
                for (int nt = 0; nt < 6; nt++) {
                    mma_tf32(c[mt][nt], ah[mt], bl[nt]);   // hi x lo
                    mma_tf32(c[mt][nt], al[mt], bh[nt]);   // lo x hi
                    mma_tf32(c[mt][nt], ah[mt], bh[nt]);   // hi x hi
                }
        }
        __syncthreads();
    }

    // Epilogue: BN + ReLU, write g_r[m][n]
    #pragma unroll
    for (int nt = 0; nt < 6; nt++) {
        int n0 = wn*48 + nt*8 + 2*ac;
        float s0 = gamma[n0  ] * rsqrtf(var[n0  ] + 1e-5f);
        float b0 = beta[n0  ] - mean[n0  ] * s0;
        float s1 = gamma[n0+1] * rsqrtf(var[n0+1] + 1e-5f);
        float b1 = beta[n0+1] - mean[n0+1] * s1;
        #pragma unroll
        for (int mt = 0; mt < 2; mt++) {
            unsigned m0 = row0 + wm*32 + mt*16 + ar;
            float2 v01 = { fmaxf(fmaf(c[mt][nt][0], s0, b0), 0.f),
                           fmaxf(fmaf(c[mt][nt][1], s1, b1), 0.f) };
            *reinterpret_cast<float2*>(&g_r[m0*OUT1 + n0]) = v01;
            float2 v23 = { fmaxf(fmaf(c[mt][nt][2], s0, b0), 0.f),
                           fmaxf(fmaf(c[mt][nt][3], s1, b1), 0.f) };
            *reinterpret_cast<float2*>(&g_r[(m0+8)*OUT1 + n0]) = v23;
        }
    }
}

// ---------------------------------------------------------------------------
// K3: per (g, h2, b): wa/wb matvecs, separable softmax kernel, apply, write
// ---------------------------------------------------------------------------
__global__ __launch_bounds__(128) void apply_kernel(
    const float* __restrict__ x,
    const float* __restrict__ w2, const float* __restrict__ b2,
    const float* __restrict__ w3, const float* __restrict__ b3,
    float* __restrict__ out)
{
    const int g = blockIdx.x, h2 = blockIdx.y, b = blockIdx.z;
    __shared__ float bufA[GCD*3*3*58];      // 33408 B: rs then xs (union)
    __shared__ float w2s[6][96];
    __shared__ float w3s[6][96];
    __shared__ float b2s[6], b3s[6];
    __shared__ float wab[WD][12];
    __shared__ float sms[WD][4][9];

    float* rs = bufA;                                            // [WD][97]
    float (*xs)[3][3][58] = reinterpret_cast<float(*)[3][3][58]>(bufA);

    const int tid = threadIdx.x;
    const unsigned posBase = (unsigned)(b*HD + h2)*WD;

    for (int idx = tid; idx < WD * OUT1; idx += 128) {
        int w = idx / OUT1, j = idx % OUT1;
        rs[w*97 + j] = g_r[posBase*OUT1 + idx];
    }
    for (int idx = tid; idx < 6 * 96; idx += 128) {
        int q = idx / 96, j = idx % 96;
        w2s[q][j] = w2[(g*6 + q)*OUT1 + j];
        w3s[q][j] = w3[(g*6 + q)*OUT1 + j];
    }
    if (tid < 6) {
        b2s[tid] = b2[g*6 + tid];
        b3s[tid] = b3[g*6 + tid];
    }
    __syncthreads();

    for (int it = tid; it < WD * 12; it += 128) {
        int q = it % 12;
        int w = it / 12;
        float acc = 0.f;
        if (q < 6) {
            #pragma unroll 8
            for (int j = 0; j < 96; j++) acc = fmaf(w2s[q][j], rs[w*97 + j], acc);
            acc += b2s[q];
        } else {
            int qq = q - 6;
            #pragma unroll 8
            for (int j = 0; j < 96; j++) acc = fmaf(w3s[qq][j], rs[w*97 + j], acc);
            acc += b3s[qq];
        }
        wab[w][q] = acc;
    }
    __syncthreads();   // rs dead; bufA reused as xs

    for (int it = tid; it < WD * 4; it += 128) {
        int t = it % 4;          // t = nh*2 + nw
        int w = it / 4;
        int nh = t >> 1, nw = t & 1;
        float e[9], m = -1e30f;
        #pragma unroll
        for (int kk = 0; kk < 9; kk++) {
            int kh = kk / 3, kw = kk % 3;
            e[kk] = wab[w][kh*2 + nh] * wab[w][6 + kw*2 + nw];
            m = fmaxf(m, e[kk]);
        }
        float s = 0.f;
        #pragma unroll
        for (int kk = 0; kk < 9; kk++) { e[kk] = expf(e[kk] - m); s += e[kk]; }
        float inv = 1.f / (s * 9.f);
        #pragma unroll
        for (int kk = 0; kk < 9; kk++) sms[w][t][kk] = e[kk] * inv;
    }
    load_taps(x, b, g, h2, xs, tid);
    __syncthreads();

    const int jv0 = h2 % 3, jv1 = (56 + h2) % 3, jv2 = (112 + h2) % 3;
    const int jvv[3] = {jv0, jv1, jv2};

    for (int it = tid; it < GCD * WD; it += 128) {
        int w  = it % WD;
        int gc = it / WD;
        float o[4] = {0.f, 0.f, 0.f, 0.f};
        #pragma unroll
        for (int kk = 0; kk < 9; kk++) {
            int kh = kk / 3, kw = kk % 3;
            float u = xs[gc][kw][kh][w + jvv[kw]];
            #pragma unroll
            for (int t = 0; t < 4; t++)
                o[t] = fmaf(u, sms[w][t][kk], o[t]);
        }
        int c = g*GCD + gc;
        #pragma unroll
        for (int t = 0; t < 4; t++) {
            int nh = t >> 1, nw = t & 1;
            out[(((unsigned)(b*CD + c))*OWD + 2*h2 + nh)*OWD + 2*w + nw] = o[t];
        }
    }
}

// ---------------------------------------------------------------------------
extern "C" void kernel_launch(void* const* d_in, const int* in_sizes, int n_in,
                              void* d_out, int out_size) {
    const float* x     = (const float*)d_in[0];
    const float* w1    = (const float*)d_in[1];
    const float* gamma = (const float*)d_in[2];
    const float* beta  = (const float*)d_in[3];
    const float* mean  = (const float*)d_in[4];
    const float* var   = (const float*)d_in[5];
    const float* w2    = (const float*)d_in[6];
    const float* b2    = (const float*)d_in[7];
    const float* w3    = (const float*)d_in[8];
    const float* b3    = (const float*)d_in[9];
    float* out = (float*)d_out;

    dim3 gridA(GD, HD, BD);   // (16, 56, 4)
    desc_kernel<<<gridA, 128>>>(x);
    gemm_tc_kernel<<<POSN / GBM, 256>>>(w1, gamma, beta, mean, var);
    apply_kernel<<<gridA, 128>>>(x, w2, b2, w3, b3, out);
}